// round 12
// baseline (speedup 1.0000x reference)
#include <cuda_runtime.h>

// ---------------------------------------------------------------------------
// SpikingNeuralNetwork: 100-step LIF sim, batch-shared sparse formulation v2.
// One batch per WARP (no intra-warp divergence): warp walks its batch's spike
// bitmask word-ascending + ffs-ascending (bit-identical to dense ascending-k
// FMA chain within each Eigen kc=512 block; block partials folded
// sequentially). Weight tiles staged in shared once per CTA -> W1 read 16MB,
// W2 32MB per step (L2-resident). LIF fused into epilogues.
// B=128, In=1024, H=4096, Out=1024, T=100.
// ---------------------------------------------------------------------------

#define Bsz  128
#define In_  1024
#define Hd_  4096
#define Out_ 1024
#define T_   100
#define KC   512

#define THRESH 1.0f
#define DECAY  0.95f
#define REFRAC 2.0f
#define LR     0.001f

// -------------------- persistent device state -------------------------------
__device__ float g_vi[Bsz * In_];
__device__ float g_ri[Bsz * In_];
__device__ float g_vh[Bsz * Hd_];
__device__ float g_rh[Bsz * Hd_];
__device__ float g_vo[Bsz * Out_];
__device__ float g_ro[Bsz * Out_];
__device__ float g_W1T[In_ * Hd_];              // [i][h] (STDP-updated in place)
__device__ float g_W2T[Hd_ * Out_];             // [h][o]
__device__ float g_in_spk[Bsz * In_];           // dense, for k_pre
__device__ float g_hid_spk[Bsz * Hd_];          // dense, for k_post
__device__ unsigned g_in_bits[Bsz][In_ / 32];   // 32 words per b
__device__ unsigned g_hid_bits[Bsz][Hd_ / 32];  // 128 words per b
__device__ float g_tp[In_];
__device__ float g_tn[Hd_];
__device__ float g_pre[In_];
__device__ float g_post[Hd_];
__device__ float g_both[1];

// -------------------- LIF: strictly rounded (no FMA contraction) -----------
__device__ __forceinline__ float lif_step(float I, float& v, float& r) {
    bool active = I > 0.0f;
    bool refrac = r > 0.0f;
    float v_int = __fadd_rn(__fmul_rn(v, DECAY), I);
    bool fired = active && !refrac && (v_int >= THRESH);
    float v_new = !active ? v : ((refrac || fired) ? 0.0f : v_int);
    float r_new = !active ? r : (refrac ? __fsub_rn(r, 1.0f) : (fired ? REFRAC : r));
    v = v_new;
    r = r_new;
    return fired ? 1.0f : 0.0f;
}

// -------------------- init ---------------------------------------------------
__global__ void k_init(float* __restrict__ out) {
    int idx = blockIdx.x * blockDim.x + threadIdx.x;   // covers Bsz*Hd_
    if (idx < Bsz * In_)  { g_vi[idx] = 0.0f; g_ri[idx] = 0.0f; }
    if (idx < Bsz * Out_) { g_vo[idx] = 0.0f; g_ro[idx] = 0.0f; out[idx] = 0.0f; }
    if (idx < Bsz * Hd_)  { g_vh[idx] = 0.0f; g_rh[idx] = 0.0f; }
    if (idx < In_) g_tp[idx] = 0.0f;
    if (idx < Hd_) g_tn[idx] = 0.0f;
    if (idx == 0)  g_both[0] = 0.0f;
}

// transposes write __device__ globals directly (never passed from host)
__global__ void k_trW1(const float* __restrict__ W1) {   // [Hd_][In_] -> g_W1T [In_][Hd_]
    __shared__ float t[32][33];
    int i = blockIdx.x * 32 + threadIdx.x;
    int h = blockIdx.y * 32 + threadIdx.y;
    t[threadIdx.y][threadIdx.x] = W1[h * In_ + i];
    __syncthreads();
    int i2 = blockIdx.x * 32 + threadIdx.y;
    int h2 = blockIdx.y * 32 + threadIdx.x;
    g_W1T[(size_t)i2 * Hd_ + h2] = t[threadIdx.x][threadIdx.y];
}

__global__ void k_trW2(const float* __restrict__ W2) {   // [Out_][Hd_] -> g_W2T [Hd_][Out_]
    __shared__ float t[32][33];
    int h = blockIdx.x * 32 + threadIdx.x;
    int o = blockIdx.y * 32 + threadIdx.y;
    t[threadIdx.y][threadIdx.x] = W2[o * Hd_ + h];
    __syncthreads();
    int h2 = blockIdx.x * 32 + threadIdx.y;
    int o2 = blockIdx.y * 32 + threadIdx.x;
    g_W2T[(size_t)h2 * Out_ + o2] = t[threadIdx.x][threadIdx.y];
}

// -------------------- encode + input LIF -> bitmasks -------------------------
__global__ __launch_bounds__(1024) void k_input(const float* __restrict__ x,
                                                const float* __restrict__ noise_t) {
    const int b = blockIdx.x;
    const int i = threadIdx.x;
    const int idx = b * In_ + i;
    float p = fminf(fmaxf(__fmul_rn(x[idx], 100.0f), 0.0f), 100.0f);
    p = __fmul_rn(p, 0.001f);
    float I = (noise_t[idx] < p) ? 1.0f : 0.0f;
    float v = g_vi[idx], r = g_ri[idx];
    float spk = lif_step(I, v, r);
    g_vi[idx] = v; g_ri[idx] = r; g_in_spk[idx] = spk;
    unsigned m = __ballot_sync(0xffffffffu, spk > 0.0f);
    if ((i & 31) == 0) g_in_bits[b][i >> 5] = m;
}

// -------------------- hidden GEMM: one batch per warp, W1 read once ----------
// grid 128 (32-col h-tiles), 1024 threads = 32 warps; warp does 4 batches.
// smem: full column slice 1024 x 32 floats = 128KB (dynamic).
__global__ __launch_bounds__(1024) void k_hgemm() {
    extern __shared__ float sW[];                // [1024][32], stride 32: lane==bank
    const int h0 = blockIdx.x * 32;
    const int t = threadIdx.x;
    const int w = t >> 5;
    const int lane = t & 31;

    // stage W1T column slice: 8192 float4 loads over 1024 threads
#pragma unroll
    for (int l = t; l < In_ * 8; l += 1024) {
        int row = l >> 3, c4 = l & 7;
        *(float4*)&sW[row * 32 + c4 * 4] =
            *(const float4*)(g_W1T + (size_t)row * Hd_ + h0 + c4 * 4);
    }
    __syncthreads();

#pragma unroll
    for (int pass = 0; pass < 4; pass++) {
        const int b = pass * 32 + w;
        const unsigned mlane = g_in_bits[b][lane];    // 32 words, one per lane
        float tot = 0.0f;
#pragma unroll
        for (int kb = 0; kb < 2; kb++) {              // kc=512 blocks
            float acc = 0.0f;
#pragma unroll
            for (int wdx = 0; wdx < 16; wdx++) {
                unsigned m = __shfl_sync(0xffffffffu, mlane, kb * 16 + wdx);
                int rbase = (kb * 16 + wdx) * 32;
                while (m) {
                    int j = __ffs(m) - 1; m &= m - 1;
                    acc = __fadd_rn(acc, sW[(rbase + j) * 32 + lane]);
                }
            }
            tot = __fadd_rn(tot, acc);
        }
        // fused hidden LIF for (b, h0+lane)
        const int idx = b * Hd_ + h0 + lane;
        float v = g_vh[idx], r = g_rh[idx];
        float spk = lif_step(tot, v, r);
        g_vh[idx] = v; g_rh[idx] = r; g_hid_spk[idx] = spk;
        unsigned bm = __ballot_sync(0xffffffffu, spk > 0.0f);
        if (lane == 0) g_hid_bits[b][blockIdx.x] = bm;
    }
}

// -------------------- output GEMM: one batch per warp, fused LIF + acc -------
// grid (Out_/32=32, 2 b-groups), 1024 threads = 32 warps; warp does 2 batches.
// smem: per-kc-block tile 512 x 32 floats = 64KB (dynamic).
__global__ __launch_bounds__(1024) void k_ogemm(float* __restrict__ out) {
    extern __shared__ float sW[];                // [512][32]
    const int o0 = blockIdx.x * 32;
    const int b0 = blockIdx.y * 64;
    const int t = threadIdx.x;
    const int w = t >> 5;
    const int lane = t & 31;
    const int b1 = b0 + w, b2 = b0 + 32 + w;

    float tot1 = 0.0f, tot2 = 0.0f;
    for (int kb = 0; kb < 8; kb++) {
        __syncthreads();                          // previous walk done
#pragma unroll
        for (int l = t; l < KC * 8; l += 1024) {
            int row = l >> 3, c4 = l & 7;
            *(float4*)&sW[row * 32 + c4 * 4] =
                *(const float4*)(g_W2T + (size_t)(kb * KC + row) * Out_ + o0 + c4 * 4);
        }
        __syncthreads();
        const unsigned m1l = (lane < 16) ? g_hid_bits[b1][kb * 16 + lane] : 0u;
        const unsigned m2l = (lane < 16) ? g_hid_bits[b2][kb * 16 + lane] : 0u;
        float a1 = 0.0f, a2 = 0.0f;
#pragma unroll
        for (int wdx = 0; wdx < 16; wdx++) {
            unsigned m1 = __shfl_sync(0xffffffffu, m1l, wdx);
            unsigned m2 = __shfl_sync(0xffffffffu, m2l, wdx);
            int rbase = wdx * 32;
            while (m1) {
                int j = __ffs(m1) - 1; m1 &= m1 - 1;
                a1 = __fadd_rn(a1, sW[(rbase + j) * 32 + lane]);
            }
            while (m2) {
                int j = __ffs(m2) - 1; m2 &= m2 - 1;
                a2 = __fadd_rn(a2, sW[(rbase + j) * 32 + lane]);
            }
        }
        tot1 = __fadd_rn(tot1, a1);
        tot2 = __fadd_rn(tot2, a2);
    }

    // fused output LIF + spike-count accumulation
    {
        const int idx = b1 * Out_ + o0 + lane;
        float v = g_vo[idx], r = g_ro[idx];
        float spk = lif_step(tot1, v, r);
        g_vo[idx] = v; g_ro[idx] = r;
        out[idx] = __fadd_rn(out[idx], spk);
    }
    {
        const int idx = b2 * Out_ + o0 + lane;
        float v = g_vo[idx], r = g_ro[idx];
        float spk = lif_step(tot2, v, r);
        g_vo[idx] = v; g_ro[idx] = r;
        out[idx] = __fadd_rn(out[idx], spk);
    }
}

// -------------------- STDP (every 10th step) ---------------------------------
// batch sums of 0/1 are exact integers -> any reduction order is exact.
__global__ void k_pre() {
    __shared__ float buf[4];
    const int i = blockIdx.x;             // In_
    const int b = threadIdx.x;            // 128
    float s = g_in_spk[b * In_ + i];
    for (int o = 16; o; o >>= 1) s += __shfl_down_sync(0xffffffffu, s, o);
    if ((b & 31) == 0) buf[b >> 5] = s;
    __syncthreads();
    if (b == 0) {
        float t = ((buf[0] + buf[1]) + buf[2]) + buf[3];
        float pm = __fmul_rn(t, 0.0078125f);            // /128 exact
        g_pre[i] = pm;
        g_tp[i] = __fadd_rn(__fmul_rn(0.9f, g_tp[i]), pm);
    }
}

__global__ void k_post() {
    __shared__ float buf[4];
    const int h = blockIdx.x;             // Hd_
    const int b = threadIdx.x;
    float s = g_hid_spk[b * Hd_ + h];
    for (int o = 16; o; o >>= 1) s += __shfl_down_sync(0xffffffffu, s, o);
    if ((b & 31) == 0) buf[b >> 5] = s;
    __syncthreads();
    if (b == 0) {
        float t = ((buf[0] + buf[1]) + buf[2]) + buf[3];
        float pm = __fmul_rn(t, 0.0078125f);
        g_post[h] = pm;
        g_tn[h] = __fadd_rn(__fmul_rn(0.9f, g_tn[h]), pm);
    }
}

__global__ void k_both() {
    __shared__ int bufi[16], bufh[16];
    const int t = threadIdx.x;            // 512
    int si = 0, sh = 0;
    const unsigned* ib = &g_in_bits[0][0];
    const unsigned* hb = &g_hid_bits[0][0];
    for (int j = t; j < Bsz * (In_ / 32); j += 512) si += __popc(ib[j]);
    for (int j = t; j < Bsz * (Hd_ / 32); j += 512) sh += __popc(hb[j]);
    for (int o = 16; o; o >>= 1) {
        si += __shfl_down_sync(0xffffffffu, si, o);
        sh += __shfl_down_sync(0xffffffffu, sh, o);
    }
    if ((t & 31) == 0) { bufi[t >> 5] = si; bufh[t >> 5] = sh; }
    __syncthreads();
    if (t == 0) {
        int ti = 0, th = 0;
        for (int x = 0; x < 16; x++) { ti += bufi[x]; th += bufh[x]; }
        g_both[0] = (ti > 0 && th > 0) ? 1.0f : 0.0f;
    }
}

// W1T[i,h] += LR*(tp[i]*post[h] - pre[i]*tn[h]), clip, gated by `both`.
__global__ void k_wupd() {
    if (g_both[0] == 0.0f) return;
    int idx = blockIdx.x * blockDim.x + threadIdx.x;   // In_*Hd_
    int i = idx >> 12;            // / Hd_
    int h = idx & (Hd_ - 1);      // % Hd_
    float d = __fmul_rn(LR, __fsub_rn(__fmul_rn(g_tp[i], g_post[h]),
                                      __fmul_rn(g_pre[i], g_tn[h])));
    float w = __fadd_rn(g_W1T[idx], d);
    g_W1T[idx] = fminf(fmaxf(w, -1.0f), 1.0f);
}

// -------------------- final scale --------------------------------------------
__global__ void k_scale(float* __restrict__ out) {
    int idx = blockIdx.x * blockDim.x + threadIdx.x;
    out[idx] = __fdiv_rn(out[idx], 100.0f);
}

// -------------------- launch --------------------------------------------------
extern "C" void kernel_launch(void* const* d_in, const int* in_sizes, int n_in,
                              void* d_out, int out_size) {
    const float* x     = (const float*)d_in[0];   // (B, In)
    const float* W1    = (const float*)d_in[1];   // (H, In)
    const float* W2    = (const float*)d_in[2];   // (Out, H)
    const float* noise = (const float*)d_in[3];   // (T, B, In)
    float* out = (float*)d_out;                   // (B, Out)

    const int HS = In_ * 32 * (int)sizeof(float);   // 128KB
    const int OS = KC * 32 * (int)sizeof(float);    // 64KB
    cudaFuncSetAttribute(k_hgemm, cudaFuncAttributeMaxDynamicSharedMemorySize, HS);
    cudaFuncSetAttribute(k_ogemm, cudaFuncAttributeMaxDynamicSharedMemorySize, OS);

    k_init<<<(Bsz * Hd_) / 256, 256>>>(out);
    k_trW1<<<dim3(In_ / 32, Hd_ / 32), dim3(32, 32)>>>(W1);
    k_trW2<<<dim3(Hd_ / 32, Out_ / 32), dim3(32, 32)>>>(W2);

    for (int t = 0; t < T_; t++) {
        k_input<<<Bsz, 1024>>>(x, noise + (size_t)t * Bsz * In_);

        bool stdp = (t % 10) == 0;
        if (stdp) k_pre<<<In_, 128>>>();

        k_hgemm<<<Hd_ / 32, 1024, HS>>>();

        if (stdp) {
            k_post<<<Hd_, 128>>>();
            k_both<<<1, 512>>>();
            k_wupd<<<(In_ * Hd_) / 256, 256>>>();
        }

        k_ogemm<<<dim3(Out_ / 32, 2), 1024, OS>>>(out);
    }

    k_scale<<<(Bsz * Out_) / 256, 256>>>(out);
}

// round 13
// speedup vs baseline: 1.0015x; 1.0015x over previous
#include <cuda_runtime.h>

// ---------------------------------------------------------------------------
// SpikingNeuralNetwork: 100-step LIF sim, batch-shared sparse formulation v2.
// One batch per WARP (no intra-warp divergence): warp walks its batch's spike
// bitmask word-ascending + ffs-ascending (bit-identical to dense ascending-k
// FMA chain within each Eigen kc=512 block; block partials folded
// sequentially). Weight tiles staged in shared once per CTA -> W1 read 16MB,
// W2 32MB per step (L2-resident). LIF fused into epilogues.
// B=128, In=1024, H=4096, Out=1024, T=100.
// ---------------------------------------------------------------------------

#define Bsz  128
#define In_  1024
#define Hd_  4096
#define Out_ 1024
#define T_   100
#define KC   512

#define THRESH 1.0f
#define DECAY  0.95f
#define REFRAC 2.0f
#define LR     0.001f

// -------------------- persistent device state -------------------------------
__device__ float g_vi[Bsz * In_];
__device__ float g_ri[Bsz * In_];
__device__ float g_vh[Bsz * Hd_];
__device__ float g_rh[Bsz * Hd_];
__device__ float g_vo[Bsz * Out_];
__device__ float g_ro[Bsz * Out_];
__device__ float g_W1T[In_ * Hd_];              // [i][h] (STDP-updated in place)
__device__ float g_W2T[Hd_ * Out_];             // [h][o]
__device__ float g_in_spk[Bsz * In_];           // dense, for k_pre
__device__ float g_hid_spk[Bsz * Hd_];          // dense, for k_post
__device__ unsigned g_in_bits[Bsz][In_ / 32];   // 32 words per b
__device__ unsigned g_hid_bits[Bsz][Hd_ / 32];  // 128 words per b
__device__ float g_tp[In_];
__device__ float g_tn[Hd_];
__device__ float g_pre[In_];
__device__ float g_post[Hd_];
__device__ float g_both[1];

// -------------------- LIF: strictly rounded (no FMA contraction) -----------
__device__ __forceinline__ float lif_step(float I, float& v, float& r) {
    bool active = I > 0.0f;
    bool refrac = r > 0.0f;
    float v_int = __fadd_rn(__fmul_rn(v, DECAY), I);
    bool fired = active && !refrac && (v_int >= THRESH);
    float v_new = !active ? v : ((refrac || fired) ? 0.0f : v_int);
    float r_new = !active ? r : (refrac ? __fsub_rn(r, 1.0f) : (fired ? REFRAC : r));
    v = v_new;
    r = r_new;
    return fired ? 1.0f : 0.0f;
}

// -------------------- init ---------------------------------------------------
__global__ void k_init(float* __restrict__ out) {
    int idx = blockIdx.x * blockDim.x + threadIdx.x;   // covers Bsz*Hd_
    if (idx < Bsz * In_)  { g_vi[idx] = 0.0f; g_ri[idx] = 0.0f; }
    if (idx < Bsz * Out_) { g_vo[idx] = 0.0f; g_ro[idx] = 0.0f; out[idx] = 0.0f; }
    if (idx < Bsz * Hd_)  { g_vh[idx] = 0.0f; g_rh[idx] = 0.0f; }
    if (idx < In_) g_tp[idx] = 0.0f;
    if (idx < Hd_) g_tn[idx] = 0.0f;
    if (idx == 0)  g_both[0] = 0.0f;
}

// transposes write __device__ globals directly (never passed from host)
__global__ void k_trW1(const float* __restrict__ W1) {   // [Hd_][In_] -> g_W1T [In_][Hd_]
    __shared__ float t[32][33];
    int i = blockIdx.x * 32 + threadIdx.x;
    int h = blockIdx.y * 32 + threadIdx.y;
    t[threadIdx.y][threadIdx.x] = W1[h * In_ + i];
    __syncthreads();
    int i2 = blockIdx.x * 32 + threadIdx.y;
    int h2 = blockIdx.y * 32 + threadIdx.x;
    g_W1T[(size_t)i2 * Hd_ + h2] = t[threadIdx.x][threadIdx.y];
}

__global__ void k_trW2(const float* __restrict__ W2) {   // [Out_][Hd_] -> g_W2T [Hd_][Out_]
    __shared__ float t[32][33];
    int h = blockIdx.x * 32 + threadIdx.x;
    int o = blockIdx.y * 32 + threadIdx.y;
    t[threadIdx.y][threadIdx.x] = W2[o * Hd_ + h];
    __syncthreads();
    int h2 = blockIdx.x * 32 + threadIdx.y;
    int o2 = blockIdx.y * 32 + threadIdx.x;
    g_W2T[(size_t)h2 * Out_ + o2] = t[threadIdx.x][threadIdx.y];
}

// -------------------- encode + input LIF -> bitmasks -------------------------
__global__ __launch_bounds__(1024) void k_input(const float* __restrict__ x,
                                                const float* __restrict__ noise_t) {
    const int b = blockIdx.x;
    const int i = threadIdx.x;
    const int idx = b * In_ + i;
    float p = fminf(fmaxf(__fmul_rn(x[idx], 100.0f), 0.0f), 100.0f);
    p = __fmul_rn(p, 0.001f);
    float I = (noise_t[idx] < p) ? 1.0f : 0.0f;
    float v = g_vi[idx], r = g_ri[idx];
    float spk = lif_step(I, v, r);
    g_vi[idx] = v; g_ri[idx] = r; g_in_spk[idx] = spk;
    unsigned m = __ballot_sync(0xffffffffu, spk > 0.0f);
    if ((i & 31) == 0) g_in_bits[b][i >> 5] = m;
}

// -------------------- hidden GEMM: one batch per warp, W1 read once ----------
// grid 128 (32-col h-tiles), 1024 threads = 32 warps; warp does 4 batches.
// smem: full column slice 1024 x 32 floats = 128KB (dynamic).
__global__ __launch_bounds__(1024) void k_hgemm() {
    extern __shared__ float sW[];                // [1024][32], stride 32: lane==bank
    const int h0 = blockIdx.x * 32;
    const int t = threadIdx.x;
    const int w = t >> 5;
    const int lane = t & 31;

    // stage W1T column slice: 8192 float4 loads over 1024 threads
#pragma unroll
    for (int l = t; l < In_ * 8; l += 1024) {
        int row = l >> 3, c4 = l & 7;
        *(float4*)&sW[row * 32 + c4 * 4] =
            *(const float4*)(g_W1T + (size_t)row * Hd_ + h0 + c4 * 4);
    }
    __syncthreads();

#pragma unroll
    for (int pass = 0; pass < 4; pass++) {
        const int b = pass * 32 + w;
        const unsigned mlane = g_in_bits[b][lane];    // 32 words, one per lane
        float tot = 0.0f;
#pragma unroll
        for (int kb = 0; kb < 2; kb++) {              // kc=512 blocks
            float acc = 0.0f;
#pragma unroll
            for (int wdx = 0; wdx < 16; wdx++) {
                unsigned m = __shfl_sync(0xffffffffu, mlane, kb * 16 + wdx);
                int rbase = (kb * 16 + wdx) * 32;
                while (m) {
                    int j = __ffs(m) - 1; m &= m - 1;
                    acc = __fadd_rn(acc, sW[(rbase + j) * 32 + lane]);
                }
            }
            tot = __fadd_rn(tot, acc);
        }
        // fused hidden LIF for (b, h0+lane)
        const int idx = b * Hd_ + h0 + lane;
        float v = g_vh[idx], r = g_rh[idx];
        float spk = lif_step(tot, v, r);
        g_vh[idx] = v; g_rh[idx] = r; g_hid_spk[idx] = spk;
        unsigned bm = __ballot_sync(0xffffffffu, spk > 0.0f);
        if (lane == 0) g_hid_bits[b][blockIdx.x] = bm;
    }
}

// -------------------- output GEMM: one batch per warp, fused LIF + acc -------
// grid (Out_/32=32, 2 b-groups), 1024 threads = 32 warps; warp does 2 batches.
// smem: per-kc-block tile 512 x 32 floats = 64KB (dynamic).
__global__ __launch_bounds__(1024) void k_ogemm(float* __restrict__ out) {
    extern __shared__ float sW[];                // [512][32]
    const int o0 = blockIdx.x * 32;
    const int b0 = blockIdx.y * 64;
    const int t = threadIdx.x;
    const int w = t >> 5;
    const int lane = t & 31;
    const int b1 = b0 + w, b2 = b0 + 32 + w;

    float tot1 = 0.0f, tot2 = 0.0f;
    for (int kb = 0; kb < 8; kb++) {
        __syncthreads();                          // previous walk done
#pragma unroll
        for (int l = t; l < KC * 8; l += 1024) {
            int row = l >> 3, c4 = l & 7;
            *(float4*)&sW[row * 32 + c4 * 4] =
                *(const float4*)(g_W2T + (size_t)(kb * KC + row) * Out_ + o0 + c4 * 4);
        }
        __syncthreads();
        const unsigned m1l = (lane < 16) ? g_hid_bits[b1][kb * 16 + lane] : 0u;
        const unsigned m2l = (lane < 16) ? g_hid_bits[b2][kb * 16 + lane] : 0u;
        float a1 = 0.0f, a2 = 0.0f;
#pragma unroll
        for (int wdx = 0; wdx < 16; wdx++) {
            unsigned m1 = __shfl_sync(0xffffffffu, m1l, wdx);
            unsigned m2 = __shfl_sync(0xffffffffu, m2l, wdx);
            int rbase = wdx * 32;
            while (m1) {
                int j = __ffs(m1) - 1; m1 &= m1 - 1;
                a1 = __fadd_rn(a1, sW[(rbase + j) * 32 + lane]);
            }
            while (m2) {
                int j = __ffs(m2) - 1; m2 &= m2 - 1;
                a2 = __fadd_rn(a2, sW[(rbase + j) * 32 + lane]);
            }
        }
        tot1 = __fadd_rn(tot1, a1);
        tot2 = __fadd_rn(tot2, a2);
    }

    // fused output LIF + spike-count accumulation
    {
        const int idx = b1 * Out_ + o0 + lane;
        float v = g_vo[idx], r = g_ro[idx];
        float spk = lif_step(tot1, v, r);
        g_vo[idx] = v; g_ro[idx] = r;
        out[idx] = __fadd_rn(out[idx], spk);
    }
    {
        const int idx = b2 * Out_ + o0 + lane;
        float v = g_vo[idx], r = g_ro[idx];
        float spk = lif_step(tot2, v, r);
        g_vo[idx] = v; g_ro[idx] = r;
        out[idx] = __fadd_rn(out[idx], spk);
    }
}

// -------------------- STDP (every 10th step) ---------------------------------
// batch sums of 0/1 are exact integers -> any reduction order is exact.
__global__ void k_pre() {
    __shared__ float buf[4];
    const int i = blockIdx.x;             // In_
    const int b = threadIdx.x;            // 128
    float s = g_in_spk[b * In_ + i];
    for (int o = 16; o; o >>= 1) s += __shfl_down_sync(0xffffffffu, s, o);
    if ((b & 31) == 0) buf[b >> 5] = s;
    __syncthreads();
    if (b == 0) {
        float t = ((buf[0] + buf[1]) + buf[2]) + buf[3];
        float pm = __fmul_rn(t, 0.0078125f);            // /128 exact
        g_pre[i] = pm;
        g_tp[i] = __fadd_rn(__fmul_rn(0.9f, g_tp[i]), pm);
    }
}

__global__ void k_post() {
    __shared__ float buf[4];
    const int h = blockIdx.x;             // Hd_
    const int b = threadIdx.x;
    float s = g_hid_spk[b * Hd_ + h];
    for (int o = 16; o; o >>= 1) s += __shfl_down_sync(0xffffffffu, s, o);
    if ((b & 31) == 0) buf[b >> 5] = s;
    __syncthreads();
    if (b == 0) {
        float t = ((buf[0] + buf[1]) + buf[2]) + buf[3];
        float pm = __fmul_rn(t, 0.0078125f);
        g_post[h] = pm;
        g_tn[h] = __fadd_rn(__fmul_rn(0.9f, g_tn[h]), pm);
    }
}

__global__ void k_both() {
    __shared__ int bufi[16], bufh[16];
    const int t = threadIdx.x;            // 512
    int si = 0, sh = 0;
    const unsigned* ib = &g_in_bits[0][0];
    const unsigned* hb = &g_hid_bits[0][0];
    for (int j = t; j < Bsz * (In_ / 32); j += 512) si += __popc(ib[j]);
    for (int j = t; j < Bsz * (Hd_ / 32); j += 512) sh += __popc(hb[j]);
    for (int o = 16; o; o >>= 1) {
        si += __shfl_down_sync(0xffffffffu, si, o);
        sh += __shfl_down_sync(0xffffffffu, sh, o);
    }
    if ((t & 31) == 0) { bufi[t >> 5] = si; bufh[t >> 5] = sh; }
    __syncthreads();
    if (t == 0) {
        int ti = 0, th = 0;
        for (int x = 0; x < 16; x++) { ti += bufi[x]; th += bufh[x]; }
        g_both[0] = (ti > 0 && th > 0) ? 1.0f : 0.0f;
    }
}

// W1T[i,h] += LR*(tp[i]*post[h] - pre[i]*tn[h]), clip, gated by `both`.
__global__ void k_wupd() {
    if (g_both[0] == 0.0f) return;
    int idx = blockIdx.x * blockDim.x + threadIdx.x;   // In_*Hd_
    int i = idx >> 12;            // / Hd_
    int h = idx & (Hd_ - 1);      // % Hd_
    float d = __fmul_rn(LR, __fsub_rn(__fmul_rn(g_tp[i], g_post[h]),
                                      __fmul_rn(g_pre[i], g_tn[h])));
    float w = __fadd_rn(g_W1T[idx], d);
    g_W1T[idx] = fminf(fmaxf(w, -1.0f), 1.0f);
}

// -------------------- final scale --------------------------------------------
__global__ void k_scale(float* __restrict__ out) {
    int idx = blockIdx.x * blockDim.x + threadIdx.x;
    out[idx] = __fdiv_rn(out[idx], 100.0f);
}

// -------------------- launch --------------------------------------------------
extern "C" void kernel_launch(void* const* d_in, const int* in_sizes, int n_in,
                              void* d_out, int out_size) {
    const float* x     = (const float*)d_in[0];   // (B, In)
    const float* W1    = (const float*)d_in[1];   // (H, In)
    const float* W2    = (const float*)d_in[2];   // (Out, H)
    const float* noise = (const float*)d_in[3];   // (T, B, In)
    float* out = (float*)d_out;                   // (B, Out)

    const int HS = In_ * 32 * (int)sizeof(float);   // 128KB
    const int OS = KC * 32 * (int)sizeof(float);    // 64KB
    cudaFuncSetAttribute(k_hgemm, cudaFuncAttributeMaxDynamicSharedMemorySize, HS);
    cudaFuncSetAttribute(k_ogemm, cudaFuncAttributeMaxDynamicSharedMemorySize, OS);

    k_init<<<(Bsz * Hd_) / 256, 256>>>(out);
    k_trW1<<<dim3(In_ / 32, Hd_ / 32), dim3(32, 32)>>>(W1);
    k_trW2<<<dim3(Hd_ / 32, Out_ / 32), dim3(32, 32)>>>(W2);

    for (int t = 0; t < T_; t++) {
        k_input<<<Bsz, 1024>>>(x, noise + (size_t)t * Bsz * In_);

        bool stdp = (t % 10) == 0;
        if (stdp) k_pre<<<In_, 128>>>();

        k_hgemm<<<Hd_ / 32, 1024, HS>>>();

        if (stdp) {
            k_post<<<Hd_, 128>>>();
            k_both<<<1, 512>>>();
            k_wupd<<<(In_ * Hd_) / 256, 256>>>();
        }

        k_ogemm<<<dim3(Out_ / 32, 2), 1024, OS>>>(out);
    }

    k_scale<<<(Bsz * Out_) / 256, 256>>>(out);
}

// round 14
// speedup vs baseline: 1.0017x; 1.0002x over previous
#include <cuda_runtime.h>

// ---------------------------------------------------------------------------
// SpikingNeuralNetwork: 100-step LIF sim, batch-shared sparse formulation v2.
// One batch per WARP (no intra-warp divergence): warp walks its batch's spike
// bitmask word-ascending + ffs-ascending (bit-identical to dense ascending-k
// FMA chain within each Eigen kc=512 block; block partials folded
// sequentially). Weight tiles staged in shared once per CTA -> W1 read 16MB,
// W2 32MB per step (L2-resident). LIF fused into epilogues.
// B=128, In=1024, H=4096, Out=1024, T=100.
// ---------------------------------------------------------------------------

#define Bsz  128
#define In_  1024
#define Hd_  4096
#define Out_ 1024
#define T_   100
#define KC   512

#define THRESH 1.0f
#define DECAY  0.95f
#define REFRAC 2.0f
#define LR     0.001f

// -------------------- persistent device state -------------------------------
__device__ float g_vi[Bsz * In_];
__device__ float g_ri[Bsz * In_];
__device__ float g_vh[Bsz * Hd_];
__device__ float g_rh[Bsz * Hd_];
__device__ float g_vo[Bsz * Out_];
__device__ float g_ro[Bsz * Out_];
__device__ float g_W1T[In_ * Hd_];              // [i][h] (STDP-updated in place)
__device__ float g_W2T[Hd_ * Out_];             // [h][o]
__device__ float g_in_spk[Bsz * In_];           // dense, for k_pre
__device__ float g_hid_spk[Bsz * Hd_];          // dense, for k_post
__device__ unsigned g_in_bits[Bsz][In_ / 32];   // 32 words per b
__device__ unsigned g_hid_bits[Bsz][Hd_ / 32];  // 128 words per b
__device__ float g_tp[In_];
__device__ float g_tn[Hd_];
__device__ float g_pre[In_];
__device__ float g_post[Hd_];
__device__ float g_both[1];

// -------------------- LIF: strictly rounded (no FMA contraction) -----------
__device__ __forceinline__ float lif_step(float I, float& v, float& r) {
    bool active = I > 0.0f;
    bool refrac = r > 0.0f;
    float v_int = __fadd_rn(__fmul_rn(v, DECAY), I);
    bool fired = active && !refrac && (v_int >= THRESH);
    float v_new = !active ? v : ((refrac || fired) ? 0.0f : v_int);
    float r_new = !active ? r : (refrac ? __fsub_rn(r, 1.0f) : (fired ? REFRAC : r));
    v = v_new;
    r = r_new;
    return fired ? 1.0f : 0.0f;
}

// -------------------- init ---------------------------------------------------
__global__ void k_init(float* __restrict__ out) {
    int idx = blockIdx.x * blockDim.x + threadIdx.x;   // covers Bsz*Hd_
    if (idx < Bsz * In_)  { g_vi[idx] = 0.0f; g_ri[idx] = 0.0f; }
    if (idx < Bsz * Out_) { g_vo[idx] = 0.0f; g_ro[idx] = 0.0f; out[idx] = 0.0f; }
    if (idx < Bsz * Hd_)  { g_vh[idx] = 0.0f; g_rh[idx] = 0.0f; }
    if (idx < In_) g_tp[idx] = 0.0f;
    if (idx < Hd_) g_tn[idx] = 0.0f;
    if (idx == 0)  g_both[0] = 0.0f;
}

// transposes write __device__ globals directly (never passed from host)
__global__ void k_trW1(const float* __restrict__ W1) {   // [Hd_][In_] -> g_W1T [In_][Hd_]
    __shared__ float t[32][33];
    int i = blockIdx.x * 32 + threadIdx.x;
    int h = blockIdx.y * 32 + threadIdx.y;
    t[threadIdx.y][threadIdx.x] = W1[h * In_ + i];
    __syncthreads();
    int i2 = blockIdx.x * 32 + threadIdx.y;
    int h2 = blockIdx.y * 32 + threadIdx.x;
    g_W1T[(size_t)i2 * Hd_ + h2] = t[threadIdx.x][threadIdx.y];
}

__global__ void k_trW2(const float* __restrict__ W2) {   // [Out_][Hd_] -> g_W2T [Hd_][Out_]
    __shared__ float t[32][33];
    int h = blockIdx.x * 32 + threadIdx.x;
    int o = blockIdx.y * 32 + threadIdx.y;
    t[threadIdx.y][threadIdx.x] = W2[o * Hd_ + h];
    __syncthreads();
    int h2 = blockIdx.x * 32 + threadIdx.y;
    int o2 = blockIdx.y * 32 + threadIdx.x;
    g_W2T[(size_t)h2 * Out_ + o2] = t[threadIdx.x][threadIdx.y];
}

// -------------------- encode + input LIF -> bitmasks -------------------------
__global__ __launch_bounds__(1024) void k_input(const float* __restrict__ x,
                                                const float* __restrict__ noise_t) {
    const int b = blockIdx.x;
    const int i = threadIdx.x;
    const int idx = b * In_ + i;
    float p = fminf(fmaxf(__fmul_rn(x[idx], 100.0f), 0.0f), 100.0f);
    p = __fmul_rn(p, 0.001f);
    float I = (noise_t[idx] < p) ? 1.0f : 0.0f;
    float v = g_vi[idx], r = g_ri[idx];
    float spk = lif_step(I, v, r);
    g_vi[idx] = v; g_ri[idx] = r; g_in_spk[idx] = spk;
    unsigned m = __ballot_sync(0xffffffffu, spk > 0.0f);
    if ((i & 31) == 0) g_in_bits[b][i >> 5] = m;
}

// -------------------- hidden GEMM: one batch per warp, W1 read once ----------
// grid 128 (32-col h-tiles), 1024 threads = 32 warps; warp does 4 batches.
// smem: full column slice 1024 x 32 floats = 128KB (dynamic).
__global__ __launch_bounds__(1024) void k_hgemm() {
    extern __shared__ float sW[];                // [1024][32], stride 32: lane==bank
    const int h0 = blockIdx.x * 32;
    const int t = threadIdx.x;
    const int w = t >> 5;
    const int lane = t & 31;

    // stage W1T column slice: 8192 float4 loads over 1024 threads
#pragma unroll
    for (int l = t; l < In_ * 8; l += 1024) {
        int row = l >> 3, c4 = l & 7;
        *(float4*)&sW[row * 32 + c4 * 4] =
            *(const float4*)(g_W1T + (size_t)row * Hd_ + h0 + c4 * 4);
    }
    __syncthreads();

#pragma unroll
    for (int pass = 0; pass < 4; pass++) {
        const int b = pass * 32 + w;
        const unsigned mlane = g_in_bits[b][lane];    // 32 words, one per lane
        float tot = 0.0f;
#pragma unroll
        for (int kb = 0; kb < 2; kb++) {              // kc=512 blocks
            float acc = 0.0f;
#pragma unroll
            for (int wdx = 0; wdx < 16; wdx++) {
                unsigned m = __shfl_sync(0xffffffffu, mlane, kb * 16 + wdx);
                int rbase = (kb * 16 + wdx) * 32;
                while (m) {
                    int j = __ffs(m) - 1; m &= m - 1;
                    acc = __fadd_rn(acc, sW[(rbase + j) * 32 + lane]);
                }
            }
            tot = __fadd_rn(tot, acc);
        }
        // fused hidden LIF for (b, h0+lane)
        const int idx = b * Hd_ + h0 + lane;
        float v = g_vh[idx], r = g_rh[idx];
        float spk = lif_step(tot, v, r);
        g_vh[idx] = v; g_rh[idx] = r; g_hid_spk[idx] = spk;
        unsigned bm = __ballot_sync(0xffffffffu, spk > 0.0f);
        if (lane == 0) g_hid_bits[b][blockIdx.x] = bm;
    }
}

// -------------------- output GEMM: one batch per warp, fused LIF + acc -------
// grid (Out_/32=32, 2 b-groups), 1024 threads = 32 warps; warp does 2 batches.
// smem: per-kc-block tile 512 x 32 floats = 64KB (dynamic).
__global__ __launch_bounds__(1024) void k_ogemm(float* __restrict__ out) {
    extern __shared__ float sW[];                // [512][32]
    const int o0 = blockIdx.x * 32;
    const int b0 = blockIdx.y * 64;
    const int t = threadIdx.x;
    const int w = t >> 5;
    const int lane = t & 31;
    const int b1 = b0 + w, b2 = b0 + 32 + w;

    float tot1 = 0.0f, tot2 = 0.0f;
    for (int kb = 0; kb < 8; kb++) {
        __syncthreads();                          // previous walk done
#pragma unroll
        for (int l = t; l < KC * 8; l += 1024) {
            int row = l >> 3, c4 = l & 7;
            *(float4*)&sW[row * 32 + c4 * 4] =
                *(const float4*)(g_W2T + (size_t)(kb * KC + row) * Out_ + o0 + c4 * 4);
        }
        __syncthreads();
        const unsigned m1l = (lane < 16) ? g_hid_bits[b1][kb * 16 + lane] : 0u;
        const unsigned m2l = (lane < 16) ? g_hid_bits[b2][kb * 16 + lane] : 0u;
        float a1 = 0.0f, a2 = 0.0f;
#pragma unroll
        for (int wdx = 0; wdx < 16; wdx++) {
            unsigned m1 = __shfl_sync(0xffffffffu, m1l, wdx);
            unsigned m2 = __shfl_sync(0xffffffffu, m2l, wdx);
            int rbase = wdx * 32;
            while (m1) {
                int j = __ffs(m1) - 1; m1 &= m1 - 1;
                a1 = __fadd_rn(a1, sW[(rbase + j) * 32 + lane]);
            }
            while (m2) {
                int j = __ffs(m2) - 1; m2 &= m2 - 1;
                a2 = __fadd_rn(a2, sW[(rbase + j) * 32 + lane]);
            }
        }
        tot1 = __fadd_rn(tot1, a1);
        tot2 = __fadd_rn(tot2, a2);
    }

    // fused output LIF + spike-count accumulation
    {
        const int idx = b1 * Out_ + o0 + lane;
        float v = g_vo[idx], r = g_ro[idx];
        float spk = lif_step(tot1, v, r);
        g_vo[idx] = v; g_ro[idx] = r;
        out[idx] = __fadd_rn(out[idx], spk);
    }
    {
        const int idx = b2 * Out_ + o0 + lane;
        float v = g_vo[idx], r = g_ro[idx];
        float spk = lif_step(tot2, v, r);
        g_vo[idx] = v; g_ro[idx] = r;
        out[idx] = __fadd_rn(out[idx], spk);
    }
}

// -------------------- STDP (every 10th step) ---------------------------------
// batch sums of 0/1 are exact integers -> any reduction order is exact.
__global__ void k_pre() {
    __shared__ float buf[4];
    const int i = blockIdx.x;             // In_
    const int b = threadIdx.x;            // 128
    float s = g_in_spk[b * In_ + i];
    for (int o = 16; o; o >>= 1) s += __shfl_down_sync(0xffffffffu, s, o);
    if ((b & 31) == 0) buf[b >> 5] = s;
    __syncthreads();
    if (b == 0) {
        float t = ((buf[0] + buf[1]) + buf[2]) + buf[3];
        float pm = __fmul_rn(t, 0.0078125f);            // /128 exact
        g_pre[i] = pm;
        g_tp[i] = __fadd_rn(__fmul_rn(0.9f, g_tp[i]), pm);
    }
}

__global__ void k_post() {
    __shared__ float buf[4];
    const int h = blockIdx.x;             // Hd_
    const int b = threadIdx.x;
    float s = g_hid_spk[b * Hd_ + h];
    for (int o = 16; o; o >>= 1) s += __shfl_down_sync(0xffffffffu, s, o);
    if ((b & 31) == 0) buf[b >> 5] = s;
    __syncthreads();
    if (b == 0) {
        float t = ((buf[0] + buf[1]) + buf[2]) + buf[3];
        float pm = __fmul_rn(t, 0.0078125f);
        g_post[h] = pm;
        g_tn[h] = __fadd_rn(__fmul_rn(0.9f, g_tn[h]), pm);
    }
}

__global__ void k_both() {
    __shared__ int bufi[16], bufh[16];
    const int t = threadIdx.x;            // 512
    int si = 0, sh = 0;
    const unsigned* ib = &g_in_bits[0][0];
    const unsigned* hb = &g_hid_bits[0][0];
    for (int j = t; j < Bsz * (In_ / 32); j += 512) si += __popc(ib[j]);
    for (int j = t; j < Bsz * (Hd_ / 32); j += 512) sh += __popc(hb[j]);
    for (int o = 16; o; o >>= 1) {
        si += __shfl_down_sync(0xffffffffu, si, o);
        sh += __shfl_down_sync(0xffffffffu, sh, o);
    }
    if ((t & 31) == 0) { bufi[t >> 5] = si; bufh[t >> 5] = sh; }
    __syncthreads();
    if (t == 0) {
        int ti = 0, th = 0;
        for (int x = 0; x < 16; x++) { ti += bufi[x]; th += bufh[x]; }
        g_both[0] = (ti > 0 && th > 0) ? 1.0f : 0.0f;
    }
}

// W1T[i,h] += LR*(tp[i]*post[h] - pre[i]*tn[h]), clip, gated by `both`.
__global__ void k_wupd() {
    if (g_both[0] == 0.0f) return;
    int idx = blockIdx.x * blockDim.x + threadIdx.x;   // In_*Hd_
    int i = idx >> 12;            // / Hd_
    int h = idx & (Hd_ - 1);      // % Hd_
    float d = __fmul_rn(LR, __fsub_rn(__fmul_rn(g_tp[i], g_post[h]),
                                      __fmul_rn(g_pre[i], g_tn[h])));
    float w = __fadd_rn(g_W1T[idx], d);
    g_W1T[idx] = fminf(fmaxf(w, -1.0f), 1.0f);
}

// -------------------- final scale --------------------------------------------
__global__ void k_scale(float* __restrict__ out) {
    int idx = blockIdx.x * blockDim.x + threadIdx.x;
    out[idx] = __fdiv_rn(out[idx], 100.0f);
}

// -------------------- launch --------------------------------------------------
extern "C" void kernel_launch(void* const* d_in, const int* in_sizes, int n_in,
                              void* d_out, int out_size) {
    const float* x     = (const float*)d_in[0];   // (B, In)
    const float* W1    = (const float*)d_in[1];   // (H, In)
    const float* W2    = (const float*)d_in[2];   // (Out, H)
    const float* noise = (const float*)d_in[3];   // (T, B, In)
    float* out = (float*)d_out;                   // (B, Out)

    const int HS = In_ * 32 * (int)sizeof(float);   // 128KB
    const int OS = KC * 32 * (int)sizeof(float);    // 64KB
    cudaFuncSetAttribute(k_hgemm, cudaFuncAttributeMaxDynamicSharedMemorySize, HS);
    cudaFuncSetAttribute(k_ogemm, cudaFuncAttributeMaxDynamicSharedMemorySize, OS);

    k_init<<<(Bsz * Hd_) / 256, 256>>>(out);
    k_trW1<<<dim3(In_ / 32, Hd_ / 32), dim3(32, 32)>>>(W1);
    k_trW2<<<dim3(Hd_ / 32, Out_ / 32), dim3(32, 32)>>>(W2);

    for (int t = 0; t < T_; t++) {
        k_input<<<Bsz, 1024>>>(x, noise + (size_t)t * Bsz * In_);

        bool stdp = (t % 10) == 0;
        if (stdp) k_pre<<<In_, 128>>>();

        k_hgemm<<<Hd_ / 32, 1024, HS>>>();

        if (stdp) {
            k_post<<<Hd_, 128>>>();
            k_both<<<1, 512>>>();
            k_wupd<<<(In_ * Hd_) / 256, 256>>>();
        }

        k_ogemm<<<dim3(Out_ / 32, 2), 1024, OS>>>(out);
    }

    k_scale<<<(Bsz * Out_) / 256, 256>>>(out);
}